// round 7
// baseline (speedup 1.0000x reference)
#include <cuda_runtime.h>
#include <cuda_fp16.h>
#include <math.h>
#include <stdint.h>

#define BS_N 4
#define SL_N 2048
#define DM_N 1024
#define NH_N 16
#define HD_N 64
#define ROWS_N (BS_N * SL_N)          // 8192
#define QKV_COLS (3 * DM_N)           // 3072
#define LOG2E_F 1.4426950408889634f

// Scratch (no runtime allocation allowed)
__device__ __half g_qkvh[(size_t)ROWS_N * QKV_COLS];   // 50 MB
__device__ __half g_attnh[(size_t)ROWS_N * DM_N];      // 16 MB
__device__ __half g_xh[(size_t)ROWS_N * DM_N];         // 16 MB
__device__ __half g_wqkvT[(size_t)QKV_COLS * DM_N];    // w_qkv^T [N][K]
__device__ __half g_wprojT[(size_t)DM_N * DM_N];       // w_proj^T [N][K]

// ---------------------------------------------------------------------------
// helpers
// ---------------------------------------------------------------------------
__device__ __forceinline__ void mma_f16(float c[4], const unsigned a[4],
                                        const unsigned b[2]) {
    asm volatile(
        "mma.sync.aligned.m16n8k16.row.col.f32.f16.f16.f32 "
        "{%0,%1,%2,%3},{%4,%5,%6,%7},{%8,%9},{%0,%1,%2,%3};"
        : "+f"(c[0]), "+f"(c[1]), "+f"(c[2]), "+f"(c[3])
        : "r"(a[0]), "r"(a[1]), "r"(a[2]), "r"(a[3]), "r"(b[0]), "r"(b[1]));
}

__device__ __forceinline__ void ldsm4(unsigned r[4], uint32_t addr) {
    asm volatile("ldmatrix.sync.aligned.m8n8.x4.shared.b16 {%0,%1,%2,%3}, [%4];"
                 : "=r"(r[0]), "=r"(r[1]), "=r"(r[2]), "=r"(r[3]) : "r"(addr));
}
__device__ __forceinline__ void ldsm4t(unsigned r[4], uint32_t addr) {
    asm volatile("ldmatrix.sync.aligned.m8n8.x4.trans.shared.b16 {%0,%1,%2,%3}, [%4];"
                 : "=r"(r[0]), "=r"(r[1]), "=r"(r[2]), "=r"(r[3]) : "r"(addr));
}

__device__ __forceinline__ void cp16cg(uint32_t dst_smem, const void* src) {
    asm volatile("cp.async.cg.shared.global [%0], [%1], 16;\n"
                 :: "r"(dst_smem), "l"(src));
}
__device__ __forceinline__ void cp_commit() {
    asm volatile("cp.async.commit_group;\n");
}

__device__ __forceinline__ unsigned packh2(float a, float b) {
    __half2 h = __floats2half2_rn(a, b);
    return *reinterpret_cast<unsigned*>(&h);
}

// ---------------------------------------------------------------------------
// Prologue kernels
// ---------------------------------------------------------------------------
__global__ void f2h_kernel(const float* __restrict__ in,
                           __half* __restrict__ outp, int n)
{
    int i = (blockIdx.x * blockDim.x + threadIdx.x) * 4;
    if (i < n) {
        float4 v = *(const float4*)(in + i);
        *(__half2*)(outp + i)     = __floats2half2_rn(v.x, v.y);
        *(__half2*)(outp + i + 2) = __floats2half2_rn(v.z, v.w);
    }
}

__global__ void transpose_h_kernel(const float* __restrict__ in,
                                   __half* __restrict__ outp, int K, int N)
{
    __shared__ float tile[32][33];
    int n0 = blockIdx.x * 32, k0 = blockIdx.y * 32;
    int tx = threadIdx.x, ty = threadIdx.y;     // 32 x 8
    #pragma unroll
    for (int j = 0; j < 32; j += 8)
        tile[ty + j][tx] = in[(size_t)(k0 + ty + j) * N + n0 + tx];
    __syncthreads();
    #pragma unroll
    for (int j = 0; j < 32; j += 8)
        outp[(size_t)(n0 + ty + j) * K + k0 + tx] = __float2half(tile[tx][ty + j]);
}

// ---------------------------------------------------------------------------
// fp16 GEMM v2: C[M,N] = A[M,K] @ B[N,K]^T. Block 128x128, 4 warps,
// warp tile 64x64 (4 mma per ldsm4), BK=32, 4-stage cp.async pipeline.
// Tile layout: row r = 64B (32 half), 16B chunk c: off = r*64+((c^((r>>1)&3))<<4).
// ---------------------------------------------------------------------------
#define STG_BYTES 16384               // A 8KB + B 8KB
#define GEMM_SMEM (4 * STG_BYTES)     // 65536

template <bool HALF_OUT>
__global__ void __launch_bounds__(128) gemm_f16(
    const __half* __restrict__ A, const __half* __restrict__ B,
    void* __restrict__ Cv, int N, int K)
{
    extern __shared__ __align__(128) char smem[];
    const uint32_t sbase = (uint32_t)__cvta_generic_to_shared(smem);
    const int tid = threadIdx.x;
    const int warp = tid >> 5, lane = tid & 31;
    const int wm = (warp & 1) * 64;
    const int wn = (warp >> 1) * 64;
    const size_t bm = (size_t)blockIdx.y * 128;
    const size_t bn = (size_t)blockIdx.x * 128;

    float acc[4][8][4];
    #pragma unroll
    for (int mi = 0; mi < 4; mi++)
        #pragma unroll
        for (int nj = 0; nj < 8; nj++)
            #pragma unroll
            for (int r = 0; r < 4; r++) acc[mi][nj][r] = 0.f;

    const char* Ab = (const char*)(A + bm * K);
    const char* Bb = (const char*)(B + bn * K);
    const size_t rowb = (size_t)K * 2;

    auto load_chunk = [&](int kc) {
        const uint32_t st = sbase + (kc & 3) * STG_BYTES;
        #pragma unroll
        for (int i = 0; i < 4; i++) {
            int idx = tid + i * 128;
            int r = idx >> 2, c = idx & 3;
            uint32_t off = r * 64 + ((c ^ ((r >> 1) & 3)) << 4);
            cp16cg(st + off, Ab + (size_t)r * rowb + kc * 64 + c * 16);
            cp16cg(st + 8192 + off, Bb + (size_t)r * rowb + kc * 64 + c * 16);
        }
        cp_commit();
    };

    const int NC = K / 32;            // 32
    load_chunk(0); load_chunk(1);

    for (int kc = 0; kc < NC; kc++) {
        if (kc + 2 < NC) load_chunk(kc + 2);
        const int rem = NC - 1 - kc;
        if (rem >= 2)      asm volatile("cp.async.wait_group 2;\n" ::: "memory");
        else if (rem == 1) asm volatile("cp.async.wait_group 1;\n" ::: "memory");
        else               asm volatile("cp.async.wait_group 0;\n" ::: "memory");
        __syncthreads();

        const uint32_t sa = sbase + (kc & 3) * STG_BYTES;
        const uint32_t sb = sa + 8192;
        #pragma unroll
        for (int s = 0; s < 2; s++) {
            unsigned af[4][4];
            #pragma unroll
            for (int mi = 0; mi < 4; mi++) {
                int row = wm + mi * 16 + (lane & 7) + ((lane >> 3) & 1) * 8;
                int c = s * 2 + (lane >> 4);
                ldsm4(af[mi], sa + row * 64 + ((c ^ ((row >> 1) & 3)) << 4));
            }
            unsigned bf[8][2];
            #pragma unroll
            for (int nb = 0; nb < 4; nb++) {
                unsigned r4[4];
                int row = wn + nb * 16 + (lane & 7) + ((lane >> 3) & 1) * 8;
                int c = s * 2 + (lane >> 4);
                ldsm4(r4, sb + row * 64 + ((c ^ ((row >> 1) & 3)) << 4));
                bf[nb * 2][0] = r4[0]; bf[nb * 2][1] = r4[2];
                bf[nb * 2 + 1][0] = r4[1]; bf[nb * 2 + 1][1] = r4[3];
            }
            #pragma unroll
            for (int mi = 0; mi < 4; mi++)
                #pragma unroll
                for (int nj = 0; nj < 8; nj++)
                    mma_f16(acc[mi][nj], af[mi], bf[nj]);
        }
    }

    const int g = lane >> 2, t = lane & 3;
    #pragma unroll
    for (int mi = 0; mi < 4; mi++) {
        #pragma unroll
        for (int nj = 0; nj < 8; nj++) {
            size_t r0 = bm + wm + mi * 16 + g;
            size_t c0 = bn + wn + nj * 8 + 2 * t;
            if (HALF_OUT) {
                __half* C = (__half*)Cv;
                *(__half2*)(C + r0 * N + c0) =
                    __floats2half2_rn(acc[mi][nj][0], acc[mi][nj][1]);
                *(__half2*)(C + (r0 + 8) * N + c0) =
                    __floats2half2_rn(acc[mi][nj][2], acc[mi][nj][3]);
            } else {
                float* C = (float*)Cv;
                *(float2*)(C + r0 * N + c0) =
                    make_float2(acc[mi][nj][0], acc[mi][nj][1]);
                *(float2*)(C + (r0 + 8) * N + c0) =
                    make_float2(acc[mi][nj][2], acc[mi][nj][3]);
            }
        }
    }
}

// ---------------------------------------------------------------------------
// Causal attention v2: block = 128 queries of one (b,h), 4 warps, each warp
// owns 32 queries (2 m16 tiles) -> K/V fragments reused across both (4 mma
// per ldsm). 32-key tiles, double-buffered cp.async. Warp-level skip of
// fully-masked tiles. Register S->P conversion (no smem round trip).
// ---------------------------------------------------------------------------
__global__ void __launch_bounds__(128) attn_f16(
    const __half* __restrict__ qkv, __half* __restrict__ outp)
{
    __shared__ __align__(128) char smem[2 * 8192];   // buf: K 4KB + V 4KB
    const uint32_t sbase = (uint32_t)__cvta_generic_to_shared(smem);

    const int b = blockIdx.z, h = blockIdx.y, qt = blockIdx.x;
    const int tid = threadIdx.x;
    const int warp = tid >> 5, lane = tid & 31;
    const int g = lane >> 2, t = lane & 3;
    const int qbase = qt * 128;
    const int wq = qbase + warp * 32;         // warp's first query row

    const __half* kb = qkv + (size_t)(b * SL_N) * QKV_COLS + DM_N + h * HD_N;
    const __half* vb = kb + DM_N;

    // Q fragments for 2 m16 tiles (scaled by 0.125; exact in fp16)
    unsigned qa[2][4][4];
    #pragma unroll
    for (int mi = 0; mi < 2; mi++) {
        const __half2 sc = __floats2half2_rn(0.125f, 0.125f);
        const __half* q0 =
            qkv + (size_t)(b * SL_N + wq + mi * 16 + g) * QKV_COLS + h * HD_N;
        const __half* q1 = q0 + (size_t)8 * QKV_COLS;
        #pragma unroll
        for (int kf = 0; kf < 4; kf++) {
            int d0 = kf * 16 + 2 * t;
            __half2 v;
            v = __hmul2(*(const __half2*)(q0 + d0), sc);      qa[mi][kf][0] = *(unsigned*)&v;
            v = __hmul2(*(const __half2*)(q1 + d0), sc);      qa[mi][kf][1] = *(unsigned*)&v;
            v = __hmul2(*(const __half2*)(q0 + d0 + 8), sc);  qa[mi][kf][2] = *(unsigned*)&v;
            v = __hmul2(*(const __half2*)(q1 + d0 + 8), sc);  qa[mi][kf][3] = *(unsigned*)&v;
        }
    }

    float o[2][8][4];
    #pragma unroll
    for (int mi = 0; mi < 2; mi++)
        #pragma unroll
        for (int j = 0; j < 8; j++)
            #pragma unroll
            for (int r = 0; r < 4; r++) o[mi][j][r] = 0.f;
    float l[2][2] = {{0.f, 0.f}, {0.f, 0.f}};

    auto issue = [&](int kt) {
        const uint32_t st = sbase + (kt & 1) * 8192;
        #pragma unroll
        for (int i = 0; i < 2; i++) {
            int idx = tid + i * 128;
            int r = idx >> 3, c = idx & 7;
            uint32_t off = r * 128 + ((c ^ (r & 7)) << 4);
            const size_t gsrc = (size_t)(kt * 32 + r) * QKV_COLS * 2 + c * 16;
            cp16cg(st + off, (const char*)kb + gsrc);
            cp16cg(st + 4096 + off, (const char*)vb + gsrc);
        }
        cp_commit();
    };

    const int nkt = qbase / 32 + 4;           // tiles covering the block
    issue(0);

    for (int kt = 0; kt < nkt; kt++) {
        asm volatile("cp.async.wait_group 0;\n" ::: "memory");
        __syncthreads();
        if (kt + 1 < nkt) issue(kt + 1);

        // warp-level skip: this warp's queries all < kt*32 -> fully masked
        if (kt * 32 <= wq + 31) {
            const uint32_t kbuf = sbase + (kt & 1) * 8192;
            const uint32_t vbuf = kbuf + 4096;

            // S = Q @ K^T -> mask + exp -> pf
            float pf[2][4][4];
            #pragma unroll
            for (int j = 0; j < 4; j++) {
                float c4[2][4] = {{0.f, 0.f, 0.f, 0.f}, {0.f, 0.f, 0.f, 0.f}};
                #pragma unroll
                for (int dh = 0; dh < 2; dh++) {
                    unsigned r4[4];
                    int row = j * 8 + (lane & 7);
                    int c = dh * 4 + (lane >> 3);
                    ldsm4(r4, kbuf + row * 128 + ((c ^ (row & 7)) << 4));
                    unsigned b0[2] = { r4[0], r4[1] };
                    unsigned b1[2] = { r4[2], r4[3] };
                    #pragma unroll
                    for (int mi = 0; mi < 2; mi++) {
                        mma_f16(c4[mi], qa[mi][dh * 2], b0);
                        mma_f16(c4[mi], qa[mi][dh * 2 + 1], b1);
                    }
                }
                int key0 = kt * 32 + j * 8 + 2 * t;
                #pragma unroll
                for (int mi = 0; mi < 2; mi++) {
                    int qg = wq + mi * 16 + g;
                    pf[mi][j][0] = (key0     <= qg)     ? exp2f(c4[mi][0] * LOG2E_F) : 0.f;
                    pf[mi][j][1] = (key0 + 1 <= qg)     ? exp2f(c4[mi][1] * LOG2E_F) : 0.f;
                    pf[mi][j][2] = (key0     <= qg + 8) ? exp2f(c4[mi][2] * LOG2E_F) : 0.f;
                    pf[mi][j][3] = (key0 + 1 <= qg + 8) ? exp2f(c4[mi][3] * LOG2E_F) : 0.f;
                    l[mi][0] += pf[mi][j][0] + pf[mi][j][1];
                    l[mi][1] += pf[mi][j][2] + pf[mi][j][3];
                }
            }

            // O += P @ V (P C-frags repacked as A-frags in registers)
            #pragma unroll
            for (int s = 0; s < 2; s++) {
                unsigned a[2][4];
                #pragma unroll
                for (int mi = 0; mi < 2; mi++) {
                    a[mi][0] = packh2(pf[mi][2 * s][0],     pf[mi][2 * s][1]);
                    a[mi][1] = packh2(pf[mi][2 * s][2],     pf[mi][2 * s][3]);
                    a[mi][2] = packh2(pf[mi][2 * s + 1][0], pf[mi][2 * s + 1][1]);
                    a[mi][3] = packh2(pf[mi][2 * s + 1][2], pf[mi][2 * s + 1][3]);
                }
                #pragma unroll
                for (int j2 = 0; j2 < 8; j2 += 2) {
                    unsigned r4[4];
                    int row = s * 16 + (lane & 7) + ((lane >> 3) & 1) * 8;
                    int c = j2 + (lane >> 4);
                    ldsm4t(r4, vbuf + row * 128 + ((c ^ (row & 7)) << 4));
                    unsigned b0[2] = { r4[0], r4[1] };
                    unsigned b1[2] = { r4[2], r4[3] };
                    #pragma unroll
                    for (int mi = 0; mi < 2; mi++) {
                        mma_f16(o[mi][j2], a[mi], b0);
                        mma_f16(o[mi][j2 + 1], a[mi], b1);
                    }
                }
            }
        }
    }

    #pragma unroll
    for (int mi = 0; mi < 2; mi++) {
        float l0 = l[mi][0], l1 = l[mi][1];
        l0 += __shfl_xor_sync(0xffffffffu, l0, 1);
        l0 += __shfl_xor_sync(0xffffffffu, l0, 2);
        l1 += __shfl_xor_sync(0xffffffffu, l1, 1);
        l1 += __shfl_xor_sync(0xffffffffu, l1, 2);
        const float inv0 = 1.0f / l0;
        const float inv1 = 1.0f / l1;

        __half* o0 = outp + (size_t)(b * SL_N + wq + mi * 16 + g) * DM_N + h * HD_N;
        __half* o1 = o0 + (size_t)8 * DM_N;
        #pragma unroll
        for (int j2 = 0; j2 < 8; j2++) {
            int c0 = j2 * 8 + 2 * t;
            *(__half2*)(o0 + c0) =
                __floats2half2_rn(o[mi][j2][0] * inv0, o[mi][j2][1] * inv0);
            *(__half2*)(o1 + c0) =
                __floats2half2_rn(o[mi][j2][2] * inv1, o[mi][j2][3] * inv1);
        }
    }
}

// ---------------------------------------------------------------------------
extern "C" void kernel_launch(void* const* d_in, const int* in_sizes, int n_in,
                              void* d_out, int out_size)
{
    const float* x      = (const float*)d_in[0];   // (4, 2048, 1024)
    const float* w_qkv  = (const float*)d_in[1];   // (1024, 3072)
    const float* w_proj = (const float*)d_in[2];   // (1024, 1024)
    float* out          = (float*)d_out;           // (4, 2048, 1024)

    __half *qkvh, *attnh, *xh, *wqkvT, *wprojT;
    cudaGetSymbolAddress((void**)&qkvh, g_qkvh);
    cudaGetSymbolAddress((void**)&attnh, g_attnh);
    cudaGetSymbolAddress((void**)&xh, g_xh);
    cudaGetSymbolAddress((void**)&wqkvT, g_wqkvT);
    cudaGetSymbolAddress((void**)&wprojT, g_wprojT);

    cudaFuncSetAttribute(gemm_f16<true>,
                         cudaFuncAttributeMaxDynamicSharedMemorySize, GEMM_SMEM);
    cudaFuncSetAttribute(gemm_f16<false>,
                         cudaFuncAttributeMaxDynamicSharedMemorySize, GEMM_SMEM);

    // 0) Convert x to half; transpose+convert weights to [N][K] half
    {
        int nx = ROWS_N * DM_N;
        f2h_kernel<<<(nx / 4 + 255) / 256, 256>>>(x, xh, nx);
        transpose_h_kernel<<<dim3(QKV_COLS / 32, DM_N / 32), dim3(32, 8)>>>(
            w_qkv, wqkvT, DM_N, QKV_COLS);
        transpose_h_kernel<<<dim3(DM_N / 32, DM_N / 32), dim3(32, 8)>>>(
            w_proj, wprojT, DM_N, DM_N);
    }

    // 1) QKV projection (fp16 mma, half epilogue feeds attention)
    gemm_f16<true><<<dim3(QKV_COLS / 128, ROWS_N / 128), 128, GEMM_SMEM>>>(
        xh, wqkvT, qkvh, QKV_COLS, DM_N);

    // 2) Causal attention (fp16 mma, register P), half epilogue
    attn_f16<<<dim3(SL_N / 128, NH_N, BS_N), 128>>>(qkvh, attnh);

    // 3) Output projection (fp16 mma, fp32 epilogue)
    gemm_f16<false><<<dim3(DM_N / 128, ROWS_N / 128), 128, GEMM_SMEM>>>(
        attnh, wprojT, out, DM_N, DM_N);
}

// round 8
// speedup vs baseline: 1.1583x; 1.1583x over previous
#include <cuda_runtime.h>
#include <cuda_fp16.h>
#include <math.h>
#include <stdint.h>

#define BS_N 4
#define SL_N 2048
#define DM_N 1024
#define NH_N 16
#define HD_N 64
#define ROWS_N (BS_N * SL_N)          // 8192
#define QKV_COLS (3 * DM_N)           // 3072
#define LOG2E_F 1.4426950408889634f

// Scratch (no runtime allocation allowed)
__device__ __half g_qkvh[(size_t)ROWS_N * QKV_COLS];   // 50 MB
__device__ __half g_attnh[(size_t)ROWS_N * DM_N];      // 16 MB
__device__ __half g_xh[(size_t)ROWS_N * DM_N];         // 16 MB
__device__ __half g_wqkvT[(size_t)QKV_COLS * DM_N];    // w_qkv^T [N][K]
__device__ __half g_wprojT[(size_t)DM_N * DM_N];       // w_proj^T [N][K]

// ---------------------------------------------------------------------------
// helpers
// ---------------------------------------------------------------------------
__device__ __forceinline__ void mma_f16(float c[4], const unsigned a[4],
                                        const unsigned b[2]) {
    asm volatile(
        "mma.sync.aligned.m16n8k16.row.col.f32.f16.f16.f32 "
        "{%0,%1,%2,%3},{%4,%5,%6,%7},{%8,%9},{%0,%1,%2,%3};"
        : "+f"(c[0]), "+f"(c[1]), "+f"(c[2]), "+f"(c[3])
        : "r"(a[0]), "r"(a[1]), "r"(a[2]), "r"(a[3]), "r"(b[0]), "r"(b[1]));
}

__device__ __forceinline__ void ldsm4(unsigned r[4], uint32_t addr) {
    asm volatile("ldmatrix.sync.aligned.m8n8.x4.shared.b16 {%0,%1,%2,%3}, [%4];"
                 : "=r"(r[0]), "=r"(r[1]), "=r"(r[2]), "=r"(r[3]) : "r"(addr));
}
__device__ __forceinline__ void ldsm4t(unsigned r[4], uint32_t addr) {
    asm volatile("ldmatrix.sync.aligned.m8n8.x4.trans.shared.b16 {%0,%1,%2,%3}, [%4];"
                 : "=r"(r[0]), "=r"(r[1]), "=r"(r[2]), "=r"(r[3]) : "r"(addr));
}

__device__ __forceinline__ void cp16cg(uint32_t dst_smem, const void* src) {
    asm volatile("cp.async.cg.shared.global [%0], [%1], 16;\n"
                 :: "r"(dst_smem), "l"(src));
}
__device__ __forceinline__ void cp_commit() {
    asm volatile("cp.async.commit_group;\n");
}

__device__ __forceinline__ unsigned packh2(float a, float b) {
    __half2 h = __floats2half2_rn(a, b);
    return *reinterpret_cast<unsigned*>(&h);
}

// ---------------------------------------------------------------------------
// Prologue kernels
// ---------------------------------------------------------------------------
__global__ void f2h_kernel(const float* __restrict__ in,
                           __half* __restrict__ outp, int n)
{
    int i = (blockIdx.x * blockDim.x + threadIdx.x) * 4;
    if (i < n) {
        float4 v = *(const float4*)(in + i);
        *(__half2*)(outp + i)     = __floats2half2_rn(v.x, v.y);
        *(__half2*)(outp + i + 2) = __floats2half2_rn(v.z, v.w);
    }
}

__global__ void transpose_h_kernel(const float* __restrict__ in,
                                   __half* __restrict__ outp, int K, int N)
{
    __shared__ float tile[32][33];
    int n0 = blockIdx.x * 32, k0 = blockIdx.y * 32;
    int tx = threadIdx.x, ty = threadIdx.y;     // 32 x 8
    #pragma unroll
    for (int j = 0; j < 32; j += 8)
        tile[ty + j][tx] = in[(size_t)(k0 + ty + j) * N + n0 + tx];
    __syncthreads();
    #pragma unroll
    for (int j = 0; j < 32; j += 8)
        outp[(size_t)(n0 + ty + j) * K + k0 + tx] = __float2half(tile[tx][ty + j]);
}

// ---------------------------------------------------------------------------
// fp16 GEMM v3: C[M,N] = A[M,K] @ B[N,K]^T. Block 128x64, 4 warps (2m x 2n),
// warp tile 64x32 (identical inner loop to the round-6 kernel), BK=32,
// 4-stage cp.async pipeline. Small 128-thread blocks -> ~4 independent
// CTAs/SM, desynchronized barriers (the profile R6's attention kernel has).
// Tile layout: row r = 64B (32 half), 16B chunk c: off = r*64+((c^((r>>1)&3))<<4).
// ---------------------------------------------------------------------------
#define STG_BYTES 12288               // A 8KB + B 4KB
#define GEMM_SMEM (4 * STG_BYTES)     // 49152

template <bool HALF_OUT>
__global__ void __launch_bounds__(128) gemm_f16(
    const __half* __restrict__ A, const __half* __restrict__ B,
    void* __restrict__ Cv, int N, int K)
{
    extern __shared__ __align__(128) char smem[];
    const uint32_t sbase = (uint32_t)__cvta_generic_to_shared(smem);
    const int tid = threadIdx.x;
    const int warp = tid >> 5, lane = tid & 31;
    const int wm = (warp & 1) * 64;
    const int wn = (warp >> 1) * 32;
    const size_t bm = (size_t)blockIdx.y * 128;
    const size_t bn = (size_t)blockIdx.x * 64;

    float acc[4][4][4];
    #pragma unroll
    for (int mi = 0; mi < 4; mi++)
        #pragma unroll
        for (int nj = 0; nj < 4; nj++)
            #pragma unroll
            for (int r = 0; r < 4; r++) acc[mi][nj][r] = 0.f;

    const char* Ab = (const char*)(A + bm * K);
    const char* Bb = (const char*)(B + bn * K);
    const size_t rowb = (size_t)K * 2;

    auto load_chunk = [&](int kc) {
        const uint32_t st = sbase + (kc & 3) * STG_BYTES;
        #pragma unroll
        for (int i = 0; i < 4; i++) {            // A: 128 rows x 4 chunks
            int idx = tid + i * 128;
            int r = idx >> 2, c = idx & 3;
            uint32_t off = r * 64 + ((c ^ ((r >> 1) & 3)) << 4);
            cp16cg(st + off, Ab + (size_t)r * rowb + kc * 64 + c * 16);
        }
        #pragma unroll
        for (int i = 0; i < 2; i++) {            // B: 64 rows x 4 chunks
            int idx = tid + i * 128;
            int r = idx >> 2, c = idx & 3;
            uint32_t off = r * 64 + ((c ^ ((r >> 1) & 3)) << 4);
            cp16cg(st + 8192 + off, Bb + (size_t)r * rowb + kc * 64 + c * 16);
        }
        cp_commit();
    };

    const int NC = K / 32;            // 32
    load_chunk(0); load_chunk(1);

    for (int kc = 0; kc < NC; kc++) {
        if (kc + 2 < NC) load_chunk(kc + 2);
        const int rem = NC - 1 - kc;
        if (rem >= 2)      asm volatile("cp.async.wait_group 2;\n" ::: "memory");
        else if (rem == 1) asm volatile("cp.async.wait_group 1;\n" ::: "memory");
        else               asm volatile("cp.async.wait_group 0;\n" ::: "memory");
        __syncthreads();

        const uint32_t sa = sbase + (kc & 3) * STG_BYTES;
        const uint32_t sb = sa + 8192;
        #pragma unroll
        for (int s = 0; s < 2; s++) {
            unsigned af[4][4];
            #pragma unroll
            for (int mi = 0; mi < 4; mi++) {
                int row = wm + mi * 16 + (lane & 7) + ((lane >> 3) & 1) * 8;
                int c = s * 2 + (lane >> 4);
                ldsm4(af[mi], sa + row * 64 + ((c ^ ((row >> 1) & 3)) << 4));
            }
            unsigned bf[4][2];
            #pragma unroll
            for (int nb = 0; nb < 2; nb++) {
                unsigned r4[4];
                int row = wn + nb * 16 + (lane & 7) + ((lane >> 3) & 1) * 8;
                int c = s * 2 + (lane >> 4);
                ldsm4(r4, sb + row * 64 + ((c ^ ((row >> 1) & 3)) << 4));
                bf[nb * 2][0] = r4[0]; bf[nb * 2][1] = r4[2];
                bf[nb * 2 + 1][0] = r4[1]; bf[nb * 2 + 1][1] = r4[3];
            }
            #pragma unroll
            for (int mi = 0; mi < 4; mi++)
                #pragma unroll
                for (int nj = 0; nj < 4; nj++)
                    mma_f16(acc[mi][nj], af[mi], bf[nj]);
        }
    }

    const int g = lane >> 2, t = lane & 3;
    #pragma unroll
    for (int mi = 0; mi < 4; mi++) {
        #pragma unroll
        for (int nj = 0; nj < 4; nj++) {
            size_t r0 = bm + wm + mi * 16 + g;
            size_t c0 = bn + wn + nj * 8 + 2 * t;
            if (HALF_OUT) {
                __half* C = (__half*)Cv;
                *(__half2*)(C + r0 * N + c0) =
                    __floats2half2_rn(acc[mi][nj][0], acc[mi][nj][1]);
                *(__half2*)(C + (r0 + 8) * N + c0) =
                    __floats2half2_rn(acc[mi][nj][2], acc[mi][nj][3]);
            } else {
                float* C = (float*)Cv;
                *(float2*)(C + r0 * N + c0) =
                    make_float2(acc[mi][nj][0], acc[mi][nj][1]);
                *(float2*)(C + (r0 + 8) * N + c0) =
                    make_float2(acc[mi][nj][2], acc[mi][nj][3]);
            }
        }
    }
}

// ---------------------------------------------------------------------------
// Causal attention, fp16 mma (round-6 version verbatim: 64 queries/block,
// 4 warps x m16, register S->P conversion, double-buffered cp.async K/V).
// ---------------------------------------------------------------------------
__global__ void __launch_bounds__(128) attn_f16(
    const __half* __restrict__ qkv, __half* __restrict__ outp)
{
    __shared__ __align__(128) char smem[2 * 8192];   // buf: K 4KB + V 4KB
    const uint32_t sbase = (uint32_t)__cvta_generic_to_shared(smem);

    const int b = blockIdx.z, h = blockIdx.y, qt = blockIdx.x;
    const int tid = threadIdx.x;
    const int warp = tid >> 5, lane = tid & 31;
    const int g = lane >> 2, t = lane & 3;
    const int qbase = qt * 64;
    const int q0g = qbase + warp * 16 + g;

    const __half* kb = qkv + (size_t)(b * SL_N) * QKV_COLS + DM_N + h * HD_N;
    const __half* vb = kb + DM_N;

    unsigned qa[4][4];
    {
        const __half2 sc = __floats2half2_rn(0.125f, 0.125f);
        const __half* q0 =
            qkv + (size_t)(b * SL_N + q0g) * QKV_COLS + h * HD_N;
        const __half* q1 = q0 + (size_t)8 * QKV_COLS;
        #pragma unroll
        for (int kf = 0; kf < 4; kf++) {
            int d0 = kf * 16 + 2 * t;
            __half2 v;
            v = __hmul2(*(const __half2*)(q0 + d0), sc);
            qa[kf][0] = *(unsigned*)&v;
            v = __hmul2(*(const __half2*)(q1 + d0), sc);
            qa[kf][1] = *(unsigned*)&v;
            v = __hmul2(*(const __half2*)(q0 + d0 + 8), sc);
            qa[kf][2] = *(unsigned*)&v;
            v = __hmul2(*(const __half2*)(q1 + d0 + 8), sc);
            qa[kf][3] = *(unsigned*)&v;
        }
    }

    float o[8][4];
    #pragma unroll
    for (int j = 0; j < 8; j++)
        #pragma unroll
        for (int r = 0; r < 4; r++) o[j][r] = 0.f;
    float l0 = 0.f, l1 = 0.f;

    auto issue = [&](int kt) {
        const uint32_t st = sbase + (kt & 1) * 8192;
        #pragma unroll
        for (int i = 0; i < 2; i++) {
            int idx = tid + i * 128;
            int r = idx >> 3, c = idx & 7;
            uint32_t off = r * 128 + ((c ^ (r & 7)) << 4);
            const size_t gsrc = (size_t)(kt * 32 + r) * QKV_COLS * 2 + c * 16;
            cp16cg(st + off, (const char*)kb + gsrc);
            cp16cg(st + 4096 + off, (const char*)vb + gsrc);
        }
        cp_commit();
    };

    const int nkt = qbase / 32 + 2;
    issue(0);

    for (int kt = 0; kt < nkt; kt++) {
        asm volatile("cp.async.wait_group 0;\n" ::: "memory");
        __syncthreads();
        if (kt + 1 < nkt) issue(kt + 1);

        const uint32_t kbuf = sbase + (kt & 1) * 8192;
        const uint32_t vbuf = kbuf + 4096;

        float pf[4][4];
        #pragma unroll
        for (int j = 0; j < 4; j++) {
            float c4[4] = {0.f, 0.f, 0.f, 0.f};
            #pragma unroll
            for (int dh = 0; dh < 2; dh++) {
                unsigned r4[4];
                int row = j * 8 + (lane & 7);
                int c = dh * 4 + (lane >> 3);
                ldsm4(r4, kbuf + row * 128 + ((c ^ (row & 7)) << 4));
                unsigned b0[2] = { r4[0], r4[1] };
                unsigned b1[2] = { r4[2], r4[3] };
                mma_f16(c4, qa[dh * 2], b0);
                mma_f16(c4, qa[dh * 2 + 1], b1);
            }
            int key0 = kt * 32 + j * 8 + 2 * t;
            pf[j][0] = (key0     <= q0g)     ? exp2f(c4[0] * LOG2E_F) : 0.f;
            pf[j][1] = (key0 + 1 <= q0g)     ? exp2f(c4[1] * LOG2E_F) : 0.f;
            pf[j][2] = (key0     <= q0g + 8) ? exp2f(c4[2] * LOG2E_F) : 0.f;
            pf[j][3] = (key0 + 1 <= q0g + 8) ? exp2f(c4[3] * LOG2E_F) : 0.f;
            l0 += pf[j][0] + pf[j][1];
            l1 += pf[j][2] + pf[j][3];
        }

        #pragma unroll
        for (int s = 0; s < 2; s++) {
            unsigned a[4] = { packh2(pf[2 * s][0],     pf[2 * s][1]),
                              packh2(pf[2 * s][2],     pf[2 * s][3]),
                              packh2(pf[2 * s + 1][0], pf[2 * s + 1][1]),
                              packh2(pf[2 * s + 1][2], pf[2 * s + 1][3]) };
            #pragma unroll
            for (int j2 = 0; j2 < 8; j2 += 2) {
                unsigned r4[4];
                int row = s * 16 + (lane & 7) + ((lane >> 3) & 1) * 8;
                int c = j2 + (lane >> 4);
                ldsm4t(r4, vbuf + row * 128 + ((c ^ (row & 7)) << 4));
                unsigned b0[2] = { r4[0], r4[1] };
                unsigned b1[2] = { r4[2], r4[3] };
                mma_f16(o[j2], a, b0);
                mma_f16(o[j2 + 1], a, b1);
            }
        }
    }

    l0 += __shfl_xor_sync(0xffffffffu, l0, 1);
    l0 += __shfl_xor_sync(0xffffffffu, l0, 2);
    l1 += __shfl_xor_sync(0xffffffffu, l1, 1);
    l1 += __shfl_xor_sync(0xffffffffu, l1, 2);
    const float inv0 = 1.0f / l0;
    const float inv1 = 1.0f / l1;

    __half* o0 = outp + (size_t)(b * SL_N + q0g) * DM_N + h * HD_N;
    __half* o1 = o0 + (size_t)8 * DM_N;
    #pragma unroll
    for (int j2 = 0; j2 < 8; j2++) {
        int c0 = j2 * 8 + 2 * t;
        *(__half2*)(o0 + c0) = __floats2half2_rn(o[j2][0] * inv0, o[j2][1] * inv0);
        *(__half2*)(o1 + c0) = __floats2half2_rn(o[j2][2] * inv1, o[j2][3] * inv1);
    }
}

// ---------------------------------------------------------------------------
extern "C" void kernel_launch(void* const* d_in, const int* in_sizes, int n_in,
                              void* d_out, int out_size)
{
    const float* x      = (const float*)d_in[0];   // (4, 2048, 1024)
    const float* w_qkv  = (const float*)d_in[1];   // (1024, 3072)
    const float* w_proj = (const float*)d_in[2];   // (1024, 1024)
    float* out          = (float*)d_out;           // (4, 2048, 1024)

    __half *qkvh, *attnh, *xh, *wqkvT, *wprojT;
    cudaGetSymbolAddress((void**)&qkvh, g_qkvh);
    cudaGetSymbolAddress((void**)&attnh, g_attnh);
    cudaGetSymbolAddress((void**)&xh, g_xh);
    cudaGetSymbolAddress((void**)&wqkvT, g_wqkvT);
    cudaGetSymbolAddress((void**)&wprojT, g_wprojT);

    cudaFuncSetAttribute(gemm_f16<true>,
                         cudaFuncAttributeMaxDynamicSharedMemorySize, GEMM_SMEM);
    cudaFuncSetAttribute(gemm_f16<false>,
                         cudaFuncAttributeMaxDynamicSharedMemorySize, GEMM_SMEM);

    // 0) Convert x to half; transpose+convert weights to [N][K] half
    {
        int nx = ROWS_N * DM_N;
        f2h_kernel<<<(nx / 4 + 255) / 256, 256>>>(x, xh, nx);
        transpose_h_kernel<<<dim3(QKV_COLS / 32, DM_N / 32), dim3(32, 8)>>>(
            w_qkv, wqkvT, DM_N, QKV_COLS);
        transpose_h_kernel<<<dim3(DM_N / 32, DM_N / 32), dim3(32, 8)>>>(
            w_proj, wprojT, DM_N, DM_N);
    }

    // 1) QKV projection (fp16 mma, half epilogue feeds attention)
    gemm_f16<true><<<dim3(QKV_COLS / 64, ROWS_N / 128), 128, GEMM_SMEM>>>(
        xh, wqkvT, qkvh, QKV_COLS, DM_N);

    // 2) Causal attention (fp16 mma, register P), half epilogue
    attn_f16<<<dim3(SL_N / 64, NH_N, BS_N), 128>>>(qkvh, attnh);

    // 3) Output projection (fp16 mma, fp32 epilogue)
    gemm_f16<false><<<dim3(DM_N / 64, ROWS_N / 128), 128, GEMM_SMEM>>>(
        attnh, wprojT, out, DM_N, DM_N);
}